// round 14
// baseline (speedup 1.0000x reference)
#include <cuda_runtime.h>
#include <cuda_fp16.h>
#include <math.h>
#include <stdint.h>

#define NB 4
#define LL 4096
#define FF 256

#define OUT_S 0
#define OUT_U 16384
#define OUT_R 32768
#define OUT_A 9469952

typedef unsigned long long ull;

__device__ float g_P[NB][64][64];
__device__ float g_rnorm[NB][LL];
__device__ __half g_Us[2][NB][LL][FF];   // fp16 splits, position-major
__device__ int   g_arg[NB][LL];
__device__ ull   g_best[NB][LL];

__constant__ int c_dy[4] = {-1, -1, -1, 0};
__constant__ int c_dx[4] = {-1,  0,  1, -1};

#define CP16(dst, src) asm volatile( \
    "cp.async.cg.shared.global [%0], [%1], 16;" :: "r"(dst), "l"(src))
#define CP_COMMIT() asm volatile("cp.async.commit_group;")
#define CP_WAIT0()  asm volatile("cp.async.wait_group 0;")

#define LDSM4(r0, r1, r2, r3, addr) \
    asm volatile("ldmatrix.sync.aligned.m8n8.x4.shared.b16 {%0,%1,%2,%3}, [%4];" \
                 : "=r"(r0), "=r"(r1), "=r"(r2), "=r"(r3) : "r"(addr))

#define MMA16816(c, a, b) \
    asm volatile("mma.sync.aligned.m16n8k16.row.col.f32.f16.f16.f32 " \
                 "{%0,%1,%2,%3}, {%4,%5,%6,%7}, {%8,%9}, {%0,%1,%2,%3};" \
                 : "+f"((c)[0]), "+f"((c)[1]), "+f"((c)[2]), "+f"((c)[3]) \
                 : "r"((a)[0]), "r"((a)[1]), "r"((a)[2]), "r"((a)[3]), \
                   "r"((b)[0]), "r"((b)[1]))

__device__ __forceinline__ unsigned sortable(float v) {
    unsigned u = __float_as_uint(v);
    return (u & 0x80000000u) ? ~u : (u | 0x80000000u);
}
__device__ __forceinline__ float unsortable(unsigned s) {
    unsigned u = (s & 0x80000000u) ? (s ^ 0x80000000u) : ~s;
    return __uint_as_float(u);
}

// ---------------------------------------------------------------------------
__global__ void kP(const float* __restrict__ yhat) {
    int b = blockIdx.x;
    int n = b >> 6, y = b & 63;
    int x = threadIdx.x;
    const float* p = yhat + (((long)n * 64) * 64 + y) * 64 + x;
    float s = 0.f;
    #pragma unroll 8
    for (int c = 0; c < 64; ++c) { float v = p[(long)c * 4096]; s += v * v; }
    g_P[n][y][x] = s;
}

__global__ void kNorm() {
    int idx = blockIdx.x * blockDim.x + threadIdx.x;
    int n = idx >> 12, l = idx & 4095;
    int y = l >> 6, x = l & 63;
    float s = 0.f;
    #pragma unroll
    for (int o = 0; o < 4; ++o) {
        int yy = y + c_dy[o], xx = x + c_dx[o];
        if (yy >= 0 && xx >= 0 && xx < 64) s += g_P[n][yy][xx];
    }
    g_rnorm[n][l] = 1.0f / fmaxf(sqrtf(s), 1e-12f);
    ((ull*)g_best)[idx] = 0ull;          // reset per replay
}

// Build fp16x2 splits of normalized features, position-major [n][l][f].
__global__ void __launch_bounds__(256) kSplit(const float* __restrict__ yhat) {
    __shared__ float sT[64][65];
    int b  = blockIdx.x;                  // n*256 + fb*64 + lb
    int lb = b & 63, fb = (b >> 6) & 3, n = b >> 8;
    int tid = threadIdx.x;
    int yy = lb + c_dy[fb];
    {
        int li = tid & 63, fi0 = tid >> 6;
        int l  = lb * 64 + li;
        float rn = g_rnorm[n][l];
        int xx = li + c_dx[fb];
        bool ok = (yy >= 0) && (xx >= 0) && (xx < 64);
        #pragma unroll
        for (int it = 0; it < 16; ++it) {
            int fi = fi0 + it * 4;
            float v = 0.f;
            if (ok) v = yhat[(((long)n * 64 + fi) * 64 + yy) * 64 + xx];
            sT[li][fi] = v * rn;
        }
    }
    __syncthreads();
    {
        int lr = tid >> 2, fq = tid & 3;
        int pos = lb * 64 + lr;
        unsigned u1[8], u2[8];
        #pragma unroll
        for (int k = 0; k < 16; ++k) {
            float v = sT[lr][fq * 16 + k];
            __half h1 = __float2half(v);
            float r1 = v - __half2float(h1);
            __half h2 = __float2half(r1);
            unsigned b1 = __half_as_ushort(h1);
            unsigned b2 = __half_as_ushort(h2);
            int w = k >> 1, sh = (k & 1) * 16;
            if (sh == 0) { u1[w] = b1; u2[w] = b2; }
            else { u1[w] |= b1 << 16; u2[w] |= b2 << 16; }
        }
        int f0 = fb * 64 + fq * 16;
        *(uint4*)&g_Us[0][n][pos][f0]     = *(uint4*)&u1[0];
        *(uint4*)&g_Us[0][n][pos][f0 + 8] = *(uint4*)&u1[4];
        *(uint4*)&g_Us[1][n][pos][f0]     = *(uint4*)&u2[0];
        *(uint4*)&g_Us[1][n][pos][f0 + 8] = *(uint4*)&u2[4];
    }
}

// ---------------------------------------------------------------------------
// fp16x2 mma.sync GEMM. Tile 128m x 64l per job (job = (n, mt, 64-wide l-strip)),
// K=256 in chunks of 32 (2 sub-chunks of 16 per barrier), 3 product passes.
// 8 warps as 4m x 2l -> acc 32 regs/thread -> 3 CTAs/SM.
// Sub-chunk smem: A0[128][16] A1[128][16] B0[64][16] B1[64][16] fp16, 48B rows.
#define ROWB   48u
#define ASPL   6144u             // 128*48
#define BSPL   3072u             // 64*48
#define HALFB  18432u            // 2*ASPL + 2*BSPL
#define STAGEB 36864u            // 2 sub-chunks
#define JOBS_N 1056              // sum over mt=0..31 of 2*(mt+1)

__global__ void __launch_bounds__(256, 3) kMMA() {
    extern __shared__ __align__(16) char dsm[];
    uint32_t sbase = (uint32_t)__cvta_generic_to_shared(dsm);

    int n = blockIdx.y;
    int q = (JOBS_N - 1) - blockIdx.x;   // big-mt jobs first
    // decode: mt(mt+1) <= q < (mt+1)(mt+2),  mt in 0..31
    int mt = (int)((sqrtf(4.f * q + 1.f) - 1.f) * 0.5f);
    while ((mt + 1) * (mt + 2) <= q) ++mt;
    while (mt * (mt + 1) > q) --mt;
    int ltq = q - mt * (mt + 1);         // 0 .. 2*mt+1 (64-wide strip)
    int m0 = mt << 7, l0 = ltq << 6;
    bool alias = (ltq >= 2 * mt);        // l-strip inside A's m rows
    uint32_t aliasOff = alias ? (uint32_t)(ltq - 2 * mt) * BSPL : 0u;

    int tid  = threadIdx.x;
    int w    = tid >> 5, lane = tid & 31;
    int wm   = w & 3, wl = w >> 2;       // 4 m-warps x 2 l-warps
    int g    = lane >> 2, tig = lane & 3;

    uint32_t aoff[2], boff[2];
    #pragma unroll
    for (int mf = 0; mf < 2; ++mf)
        aoff[mf] = (uint32_t)((wm * 32 + mf * 16 + (lane & 15)) * ROWB
                              + (lane >> 4) * 16);
    #pragma unroll
    for (int p = 0; p < 2; ++p)
        boff[p] = (uint32_t)((wl * 32 + p * 16 + (lane & 7) + ((lane >> 4) << 3)) * ROWB
                             + (((lane >> 3) & 1) << 4));

    // cp.async tasks per sub-chunk: A 512, B 256 (skip B when alias)
    #define LOAD_SUB(k16, dst) do { \
        int _k0 = (k16) << 4; \
        _Pragma("unroll") \
        for (int it = 0; it < 2; ++it) { \
            int t = tid + (it << 8); \
            int sp = t >> 8, r = (t >> 1) & 127, h = t & 1; \
            const __half* src = &g_Us[sp][n][m0 + r][_k0 + h * 8]; \
            CP16((dst) + sp * ASPL + r * ROWB + (h << 4), src); \
        } \
        if (!alias && tid < 256) { \
            int sp = tid >> 7, r = (tid >> 1) & 63, h = tid & 1; \
            const __half* src = &g_Us[sp][n][l0 + r][_k0 + h * 8]; \
            CP16((dst) + 2 * ASPL + sp * BSPL + r * ROWB + (h << 4), src); \
        } \
    } while (0)

    // prefetch chunk 0 (sub-chunks 0,1)
    LOAD_SUB(0, sbase);
    LOAD_SUB(1, sbase + HALFB);
    CP_COMMIT();

    float acc[2][4][4];
    #pragma unroll
    for (int i = 0; i < 2; ++i)
        #pragma unroll
        for (int j = 0; j < 4; ++j)
            #pragma unroll
            for (int r = 0; r < 4; ++r) acc[i][j][r] = 0.f;

    unsigned af[2][4], bf[4][2];

    #pragma unroll 1
    for (int kc = 0; kc < 8; ++kc) {
        CP_WAIT0();
        __syncthreads();
        if (kc < 7) {
            uint32_t st = sbase + (uint32_t)((kc + 1) & 1) * STAGEB;
            LOAD_SUB((kc + 1) * 2,     st);
            LOAD_SUB((kc + 1) * 2 + 1, st + HALFB);
            CP_COMMIT();
        }

        uint32_t stg = sbase + (uint32_t)(kc & 1) * STAGEB;

        #define LOADA(base) do { \
            LDSM4(af[0][0], af[0][1], af[0][2], af[0][3], (base) + aoff[0]); \
            LDSM4(af[1][0], af[1][1], af[1][2], af[1][3], (base) + aoff[1]); \
        } while (0)
        #define LOADB(base) do { \
            LDSM4(bf[0][0], bf[0][1], bf[1][0], bf[1][1], (base) + boff[0]); \
            LDSM4(bf[2][0], bf[2][1], bf[3][0], bf[3][1], (base) + boff[1]); \
        } while (0)
        #define PASS() do { \
            _Pragma("unroll") \
            for (int mf = 0; mf < 2; ++mf) \
                _Pragma("unroll") \
                for (int nf = 0; nf < 4; ++nf) \
                    MMA16816(acc[mf][nf], af[mf], bf[nf]); \
        } while (0)

        #pragma unroll
        for (int h = 0; h < 2; ++h) {
            uint32_t sA = stg + h * HALFB;
            uint32_t b0 = alias ? (sA + aliasOff)          : (sA + 2 * ASPL);
            uint32_t b1 = alias ? (sA + ASPL + aliasOff)   : (sA + 2 * ASPL + BSPL);
            // order: h2*h1, h1*h1, h1*h2
            LOADA(sA + ASPL); LOADB(b0); PASS();
            LOADA(sA);                   PASS();
            LOADB(b1);                   PASS();
        }
    }

    // fold into per-thread best (causal l < m, explicit l tie-break)
    float bestv[4];
    int   bestl[4];
    #pragma unroll
    for (int s = 0; s < 4; ++s) { bestv[s] = -INFINITY; bestl[s] = 0x7fffffff; }

    #pragma unroll
    for (int mf = 0; mf < 2; ++mf) {
        #pragma unroll
        for (int rh = 0; rh < 2; ++rh) {
            int s = mf * 2 + rh;
            int m = m0 + wm * 32 + mf * 16 + g + rh * 8;
            #pragma unroll
            for (int nf = 0; nf < 4; ++nf) {
                #pragma unroll
                for (int cp = 0; cp < 2; ++cp) {
                    float v = acc[mf][nf][(rh << 1) | cp];
                    int l = l0 + wl * 32 + nf * 8 + 2 * tig + cp;
                    if (l < m && (v > bestv[s] || (v == bestv[s] && l < bestl[s]))) {
                        bestv[s] = v; bestl[s] = l;
                    }
                }
            }
        }
    }

    // cross-thread reduction: each m-row has 8 contributors (wl x tig)
    __syncthreads();
    float* rv = (float*)dsm;            // [128][8]
    int*   rl = (int*)(dsm + 4096);     // [128][8]
    #pragma unroll
    for (int mf = 0; mf < 2; ++mf)
        #pragma unroll
        for (int rh = 0; rh < 2; ++rh) {
            int mm = wm * 32 + mf * 16 + g + rh * 8;
            rv[mm * 8 + wl * 4 + tig] = bestv[mf * 2 + rh];
            rl[mm * 8 + wl * 4 + tig] = bestl[mf * 2 + rh];
        }
    __syncthreads();
    if (tid < 128) {
        float bv = rv[tid * 8];
        int   bl = rl[tid * 8];
        #pragma unroll
        for (int u = 1; u < 8; ++u) {
            float v = rv[tid * 8 + u];
            int   l = rl[tid * 8 + u];
            if (v > bv || (v == bv && l < bl)) { bv = v; bl = l; }
        }
        if (bl != 0x7fffffff) {
            bv += 0.0f;                 // canonicalize -0.0
            ull key = ((ull)sortable(bv) << 32) | (unsigned)(~bl);
            atomicMax(&g_best[n][m0 + tid], key);
        }
    }
}

// ---------------------------------------------------------------------------
__global__ void kFinal(const float* __restrict__ yprob, float* __restrict__ out) {
    int idx = blockIdx.x * blockDim.x + threadIdx.x;
    int n = idx >> 12, m = idx & 4095;
    float S, U, A;
    int bl;
    if (m == 0) {
        S = 1e-8f; U = 1e-8f; A = -1.f; bl = -1;
    } else {
        ull key = g_best[n][m];
        float bv = unsortable((unsigned)(key >> 32));
        bl = (int)(~(unsigned)(key & 0xffffffffu));
        if (bv < 0.f) { bv = 0.f; bl = m; }
        S = fminf(fmaxf(bv, 1e-8f), 1.0f);
        U = fminf(fmaxf(yprob[n * LL + bl], 1e-8f), 1.0f);
        A = (float)bl;
    }
    g_arg[n][m] = bl;
    out[OUT_S + idx] = S;
    out[OUT_U + idx] = U;
    out[OUT_A + idx] = A;
}

__global__ void kOut(const float* __restrict__ yhat, float* __restrict__ out) {
    long e = (long)blockIdx.x * blockDim.x + threadIdx.x;
    int m = (int)(e & 4095);
    int t = (int)(e >> 12);
    int f = t % 576;
    int n = t / 576;
    float v = 0.f;
    if (m != 0) {
        int a  = g_arg[n][m];
        int c  = f / 9, ij = f % 9;
        int i  = ij / 3, j = ij % 3;
        int ay = a >> 6, ax = a & 63;
        int yy = ay + i - 1, xx = ax + j - 1;
        if (yy >= 0 && yy < 64 && xx >= 0 && xx < 64)
            v = yhat[(((long)n * 64 + c) * 64 + yy) * 64 + xx];
    }
    out[OUT_R + e] = v;
}

// ---------------------------------------------------------------------------
extern "C" void kernel_launch(void* const* d_in, const int* in_sizes, int n_in,
                              void* d_out, int out_size) {
    const float* yhat  = (const float*)d_in[0];
    const float* yprob = (const float*)d_in[1];
    float* out = (float*)d_out;

    cudaFuncSetAttribute(kMMA, cudaFuncAttributeMaxDynamicSharedMemorySize,
                         2 * STAGEB);

    kP<<<NB * 64, 64>>>(yhat);
    kNorm<<<(NB * LL) / 256, 256>>>();
    kSplit<<<NB * 4 * 64, 256>>>(yhat);
    kMMA<<<dim3(JOBS_N, NB), 256, 2 * STAGEB>>>();
    kFinal<<<(NB * LL) / 256, 256>>>(yprob, out);
    kOut<<<(NB * 576 * LL) / 256, 256>>>(yhat, out);
}

// round 15
// speedup vs baseline: 1.1017x; 1.1017x over previous
#include <cuda_runtime.h>
#include <cuda_fp16.h>
#include <math.h>
#include <stdint.h>

#define NB 4
#define LL 4096
#define FF 256

#define OUT_S 0
#define OUT_U 16384
#define OUT_R 32768
#define OUT_A 9469952

typedef unsigned long long ull;

__device__ float g_P[NB][64][64];
__device__ float g_rnorm[NB][LL];
__device__ __half g_Us[2][NB][LL][FF];   // fp16 splits, position-major
__device__ int   g_arg[NB][LL];
__device__ ull   g_best[NB][LL];

__constant__ int c_dy[4] = {-1, -1, -1, 0};
__constant__ int c_dx[4] = {-1,  0,  1, -1};

#define CP16(dst, src) asm volatile( \
    "cp.async.cg.shared.global [%0], [%1], 16;" :: "r"(dst), "l"(src))
#define CP_COMMIT() asm volatile("cp.async.commit_group;")
#define CP_WAIT0()  asm volatile("cp.async.wait_group 0;")

#define LDSM4(r0, r1, r2, r3, addr) \
    asm volatile("ldmatrix.sync.aligned.m8n8.x4.shared.b16 {%0,%1,%2,%3}, [%4];" \
                 : "=r"(r0), "=r"(r1), "=r"(r2), "=r"(r3) : "r"(addr))

#define MMA16816(c, a, b) \
    asm volatile("mma.sync.aligned.m16n8k16.row.col.f32.f16.f16.f32 " \
                 "{%0,%1,%2,%3}, {%4,%5,%6,%7}, {%8,%9}, {%0,%1,%2,%3};" \
                 : "+f"((c)[0]), "+f"((c)[1]), "+f"((c)[2]), "+f"((c)[3]) \
                 : "r"((a)[0]), "r"((a)[1]), "r"((a)[2]), "r"((a)[3]), \
                   "r"((b)[0]), "r"((b)[1]))

__device__ __forceinline__ unsigned sortable(float v) {
    unsigned u = __float_as_uint(v);
    return (u & 0x80000000u) ? ~u : (u | 0x80000000u);
}
__device__ __forceinline__ float unsortable(unsigned s) {
    unsigned u = (s & 0x80000000u) ? (s ^ 0x80000000u) : ~s;
    return __uint_as_float(u);
}

// ---------------------------------------------------------------------------
__global__ void kP(const float* __restrict__ yhat) {
    int b = blockIdx.x;
    int n = b >> 6, y = b & 63;
    int x = threadIdx.x;
    const float* p = yhat + (((long)n * 64) * 64 + y) * 64 + x;
    float s = 0.f;
    #pragma unroll 8
    for (int c = 0; c < 64; ++c) { float v = p[(long)c * 4096]; s += v * v; }
    g_P[n][y][x] = s;
}

__global__ void kNorm() {
    int idx = blockIdx.x * blockDim.x + threadIdx.x;
    int n = idx >> 12, l = idx & 4095;
    int y = l >> 6, x = l & 63;
    float s = 0.f;
    #pragma unroll
    for (int o = 0; o < 4; ++o) {
        int yy = y + c_dy[o], xx = x + c_dx[o];
        if (yy >= 0 && xx >= 0 && xx < 64) s += g_P[n][yy][xx];
    }
    g_rnorm[n][l] = 1.0f / fmaxf(sqrtf(s), 1e-12f);
    ((ull*)g_best)[idx] = 0ull;          // reset per replay
}

// Build fp16x2 splits of normalized features, position-major [n][l][f].
__global__ void __launch_bounds__(256) kSplit(const float* __restrict__ yhat) {
    __shared__ float sT[64][65];
    int b  = blockIdx.x;                  // n*256 + fb*64 + lb
    int lb = b & 63, fb = (b >> 6) & 3, n = b >> 8;
    int tid = threadIdx.x;
    int yy = lb + c_dy[fb];
    {
        int li = tid & 63, fi0 = tid >> 6;
        int l  = lb * 64 + li;
        float rn = g_rnorm[n][l];
        int xx = li + c_dx[fb];
        bool ok = (yy >= 0) && (xx >= 0) && (xx < 64);
        #pragma unroll
        for (int it = 0; it < 16; ++it) {
            int fi = fi0 + it * 4;
            float v = 0.f;
            if (ok) v = yhat[(((long)n * 64 + fi) * 64 + yy) * 64 + xx];
            sT[li][fi] = v * rn;
        }
    }
    __syncthreads();
    {
        int lr = tid >> 2, fq = tid & 3;
        int pos = lb * 64 + lr;
        unsigned u1[8], u2[8];
        #pragma unroll
        for (int k = 0; k < 16; ++k) {
            float v = sT[lr][fq * 16 + k];
            __half h1 = __float2half(v);
            float r1 = v - __half2float(h1);
            __half h2 = __float2half(r1);
            unsigned b1 = __half_as_ushort(h1);
            unsigned b2 = __half_as_ushort(h2);
            int w = k >> 1, sh = (k & 1) * 16;
            if (sh == 0) { u1[w] = b1; u2[w] = b2; }
            else { u1[w] |= b1 << 16; u2[w] |= b2 << 16; }
        }
        int f0 = fb * 64 + fq * 16;
        *(uint4*)&g_Us[0][n][pos][f0]     = *(uint4*)&u1[0];
        *(uint4*)&g_Us[0][n][pos][f0 + 8] = *(uint4*)&u1[4];
        *(uint4*)&g_Us[1][n][pos][f0]     = *(uint4*)&u2[0];
        *(uint4*)&g_Us[1][n][pos][f0 + 8] = *(uint4*)&u2[4];
    }
}

// ---------------------------------------------------------------------------
// fp16x2 mma.sync GEMM. 128x128 tile per job, K=256 in chunks of 32
// (2 sub-chunks of 16 per barrier). 3 product passes with BOTH B halves
// register-resident (bf1, bf2) so the final pass has no pending LDSM.
// smem stage: 2 sub-chunks x {A-h1, A-h2, B-h1, B-h2} each 128x16 fp16, 48B rows.
#define ROWB   48u
#define SPLITB 6144u             // 128*48
#define HALFB  24576u            // 4*SPLITB (one sub-chunk)
#define STAGEB 49152u            // 2 sub-chunks

__global__ void __launch_bounds__(256, 2) kMMA() {
    extern __shared__ __align__(16) char dsm[];
    uint32_t sbase = (uint32_t)__cvta_generic_to_shared(dsm);

    int n = blockIdx.y;
    int b = blockIdx.x;                 // b = mt*(mt+1)/2 + lt
    int mt = (int)((sqrtf(8.f * b + 1.f) - 1.f) * 0.5f);
    while ((mt + 1) * (mt + 2) / 2 <= b) ++mt;
    while (mt * (mt + 1) / 2 > b) --mt;
    int lt = b - mt * (mt + 1) / 2;
    int m0 = mt << 7, l0 = lt << 7;
    bool diag = (lt == mt);
    uint32_t bTile = diag ? 0u : 2u;    // diag: B aliases A tiles

    int tid  = threadIdx.x;
    int w    = tid >> 5, lane = tid & 31;
    int wm   = w & 1, wl = w >> 1;
    int g    = lane >> 2, tig = lane & 3;

    int crow = tid >> 1, chalf = tid & 1;   // cp.async task: (row, 16B half)

    uint32_t aoff[4], boff[2];
    #pragma unroll
    for (int im = 0; im < 4; ++im)
        aoff[im] = (uint32_t)((wm * 64 + im * 16 + (lane & 15)) * ROWB
                              + (lane >> 4) * 16);
    #pragma unroll
    for (int p = 0; p < 2; ++p)
        boff[p] = (uint32_t)((wl * 32 + p * 16 + (lane & 7) + ((lane >> 4) << 3)) * ROWB
                             + (((lane >> 3) & 1) << 4));

    // prefetch chunk 0 (both sub-chunks)
    {
        #pragma unroll
        for (int h = 0; h < 2; ++h) {
            #pragma unroll
            for (int tile = 0; tile < 4; ++tile) {
                if (tile >= 2 && diag) break;
                int sp = tile & 1; bool isB = tile >= 2;
                const __half* src =
                    &g_Us[sp][n][(isB ? l0 : m0) + crow][h * 16] + (chalf << 3);
                CP16(sbase + h * HALFB + tile * SPLITB + crow * ROWB + (chalf << 4), src);
            }
        }
        CP_COMMIT();
    }

    float acc[4][4][4];
    #pragma unroll
    for (int i = 0; i < 4; ++i)
        #pragma unroll
        for (int j = 0; j < 4; ++j)
            #pragma unroll
            for (int r = 0; r < 4; ++r) acc[i][j][r] = 0.f;

    unsigned af[4][4], bf1[4][2], bf2[4][2];

    #pragma unroll 1
    for (int kc = 0; kc < 8; ++kc) {
        CP_WAIT0();
        __syncthreads();
        if (kc < 7) {                   // prefetch next 32-k chunk
            int k0 = (kc + 1) << 5;
            uint32_t st = sbase + (uint32_t)((kc + 1) & 1) * STAGEB;
            #pragma unroll
            for (int h = 0; h < 2; ++h) {
                #pragma unroll
                for (int tile = 0; tile < 4; ++tile) {
                    if (tile >= 2 && diag) break;
                    int sp = tile & 1; bool isB = tile >= 2;
                    const __half* src =
                        &g_Us[sp][n][(isB ? l0 : m0) + crow][k0 + h * 16] + (chalf << 3);
                    CP16(st + h * HALFB + tile * SPLITB + crow * ROWB + (chalf << 4), src);
                }
            }
            CP_COMMIT();
        }

        uint32_t stg = sbase + (uint32_t)(kc & 1) * STAGEB;

        #define LOADA(base) do { \
            LDSM4(af[0][0], af[0][1], af[0][2], af[0][3], (base) + aoff[0]); \
            LDSM4(af[1][0], af[1][1], af[1][2], af[1][3], (base) + aoff[1]); \
            LDSM4(af[2][0], af[2][1], af[2][2], af[2][3], (base) + aoff[2]); \
            LDSM4(af[3][0], af[3][1], af[3][2], af[3][3], (base) + aoff[3]); \
        } while (0)
        #define LOADBx(bfx, base) do { \
            LDSM4(bfx[0][0], bfx[0][1], bfx[1][0], bfx[1][1], (base) + boff[0]); \
            LDSM4(bfx[2][0], bfx[2][1], bfx[3][0], bfx[3][1], (base) + boff[1]); \
        } while (0)
        #define PASSx(bfx) do { \
            _Pragma("unroll") \
            for (int im = 0; im < 4; ++im) \
                _Pragma("unroll") \
                for (int in = 0; in < 4; ++in) \
                    MMA16816(acc[im][in], af[im], bfx[in]); \
        } while (0)

        #pragma unroll
        for (int h = 0; h < 2; ++h) {
            uint32_t sA = stg + h * HALFB;
            uint32_t sB = sA + bTile * SPLITB;
            // h2*h1, then h1*h1, then h1*h2 (bf2 preloaded -> no LDSM before it)
            LOADA(sA + SPLITB);
            LOADBx(bf1, sB);
            LOADBx(bf2, sB + SPLITB);
            PASSx(bf1);
            LOADA(sA);
            PASSx(bf1);
            PASSx(bf2);
        }
    }

    // fold into per-thread best (causal l < m, explicit l tie-break)
    float bestv[8];
    int   bestl[8];
    #pragma unroll
    for (int s = 0; s < 8; ++s) { bestv[s] = -INFINITY; bestl[s] = 0x7fffffff; }

    #pragma unroll
    for (int im = 0; im < 4; ++im) {
        #pragma unroll
        for (int rh = 0; rh < 2; ++rh) {
            int s = im * 2 + rh;
            int m = m0 + wm * 64 + im * 16 + g + rh * 8;
            #pragma unroll
            for (int in = 0; in < 4; ++in) {
                #pragma unroll
                for (int cp = 0; cp < 2; ++cp) {
                    float v = acc[im][in][(rh << 1) | cp];
                    int l = l0 + wl * 32 + in * 8 + 2 * tig + cp;
                    if (l < m && (v > bestv[s] || (v == bestv[s] && l < bestl[s]))) {
                        bestv[s] = v; bestl[s] = l;
                    }
                }
            }
        }
    }

    // cross-thread reduction: m-row has 16 contributors (wl x tig)
    __syncthreads();
    float* rv = (float*)dsm;            // [128][16]
    int*   rl = (int*)(dsm + 8192);     // [128][16]
    #pragma unroll
    for (int im = 0; im < 4; ++im)
        #pragma unroll
        for (int rh = 0; rh < 2; ++rh) {
            int mm = wm * 64 + im * 16 + g + rh * 8;
            rv[mm * 16 + wl * 4 + tig] = bestv[im * 2 + rh];
            rl[mm * 16 + wl * 4 + tig] = bestl[im * 2 + rh];
        }
    __syncthreads();
    if (tid < 128) {
        float bv = rv[tid * 16];
        int   bl = rl[tid * 16];
        #pragma unroll
        for (int u = 1; u < 16; ++u) {
            float v = rv[tid * 16 + u];
            int   l = rl[tid * 16 + u];
            if (v > bv || (v == bv && l < bl)) { bv = v; bl = l; }
        }
        bv += 0.0f;                     // canonicalize -0.0
        ull key = ((ull)sortable(bv) << 32) | (unsigned)(~bl);
        atomicMax(&g_best[n][m0 + tid], key);
    }
}

// ---------------------------------------------------------------------------
__global__ void kFinal(const float* __restrict__ yprob, float* __restrict__ out) {
    int idx = blockIdx.x * blockDim.x + threadIdx.x;
    int n = idx >> 12, m = idx & 4095;
    float S, U, A;
    int bl;
    if (m == 0) {
        S = 1e-8f; U = 1e-8f; A = -1.f; bl = -1;
    } else {
        ull key = g_best[n][m];
        float bv = unsortable((unsigned)(key >> 32));
        bl = (int)(~(unsigned)(key & 0xffffffffu));
        if (bv < 0.f) { bv = 0.f; bl = m; }
        S = fminf(fmaxf(bv, 1e-8f), 1.0f);
        U = fminf(fmaxf(yprob[n * LL + bl], 1e-8f), 1.0f);
        A = (float)bl;
    }
    g_arg[n][m] = bl;
    out[OUT_S + idx] = S;
    out[OUT_U + idx] = U;
    out[OUT_A + idx] = A;
}

__global__ void kOut(const float* __restrict__ yhat, float* __restrict__ out) {
    long e = (long)blockIdx.x * blockDim.x + threadIdx.x;
    int m = (int)(e & 4095);
    int t = (int)(e >> 12);
    int f = t % 576;
    int n = t / 576;
    float v = 0.f;
    if (m != 0) {
        int a  = g_arg[n][m];
        int c  = f / 9, ij = f % 9;
        int i  = ij / 3, j = ij % 3;
        int ay = a >> 6, ax = a & 63;
        int yy = ay + i - 1, xx = ax + j - 1;
        if (yy >= 0 && yy < 64 && xx >= 0 && xx < 64)
            v = yhat[(((long)n * 64 + c) * 64 + yy) * 64 + xx];
    }
    out[OUT_R + e] = v;
}

// ---------------------------------------------------------------------------
extern "C" void kernel_launch(void* const* d_in, const int* in_sizes, int n_in,
                              void* d_out, int out_size) {
    const float* yhat  = (const float*)d_in[0];
    const float* yprob = (const float*)d_in[1];
    float* out = (float*)d_out;

    cudaFuncSetAttribute(kMMA, cudaFuncAttributeMaxDynamicSharedMemorySize,
                         2 * STAGEB);

    kP<<<NB * 64, 64>>>(yhat);
    kNorm<<<(NB * LL) / 256, 256>>>();
    kSplit<<<NB * 4 * 64, 256>>>(yhat);
    kMMA<<<dim3(528, NB), 256, 2 * STAGEB>>>();
    kFinal<<<(NB * LL) / 256, 256>>>(yprob, out);
    kOut<<<(NB * 576 * LL) / 256, 256>>>(yhat, out);
}

// round 16
// speedup vs baseline: 1.1546x; 1.0480x over previous
#include <cuda_runtime.h>
#include <cuda_fp16.h>
#include <math.h>
#include <stdint.h>

#define NB 4
#define LL 4096
#define FF 256

#define OUT_S 0
#define OUT_U 16384
#define OUT_R 32768
#define OUT_A 9469952

typedef unsigned long long ull;

__device__ float g_P[NB][64][64];
__device__ float g_rnorm[NB][LL];
__device__ __half g_Us[2][NB][LL][FF];   // fp16 splits, position-major
__device__ int   g_arg[NB][LL];
__device__ ull   g_best[NB][LL];

__constant__ int c_dy[4] = {-1, -1, -1, 0};
__constant__ int c_dx[4] = {-1,  0,  1, -1};

#define CP16(dst, src) asm volatile( \
    "cp.async.cg.shared.global [%0], [%1], 16;" :: "r"(dst), "l"(src))
#define CP_COMMIT() asm volatile("cp.async.commit_group;")
#define CP_WAIT0()  asm volatile("cp.async.wait_group 0;")

#define LDSM4(r0, r1, r2, r3, addr) \
    asm volatile("ldmatrix.sync.aligned.m8n8.x4.shared.b16 {%0,%1,%2,%3}, [%4];" \
                 : "=r"(r0), "=r"(r1), "=r"(r2), "=r"(r3) : "r"(addr))

#define MMA16816(c, a, b) \
    asm volatile("mma.sync.aligned.m16n8k16.row.col.f32.f16.f16.f32 " \
                 "{%0,%1,%2,%3}, {%4,%5,%6,%7}, {%8,%9}, {%0,%1,%2,%3};" \
                 : "+f"((c)[0]), "+f"((c)[1]), "+f"((c)[2]), "+f"((c)[3]) \
                 : "r"((a)[0]), "r"((a)[1]), "r"((a)[2]), "r"((a)[3]), \
                   "r"((b)[0]), "r"((b)[1]))

__device__ __forceinline__ unsigned sortable(float v) {
    unsigned u = __float_as_uint(v);
    return (u & 0x80000000u) ? ~u : (u | 0x80000000u);
}
__device__ __forceinline__ float unsortable(unsigned s) {
    unsigned u = (s & 0x80000000u) ? (s ^ 0x80000000u) : ~s;
    return __uint_as_float(u);
}

// ---------------------------------------------------------------------------
__global__ void kP(const float* __restrict__ yhat) {
    int b = blockIdx.x;
    int n = b >> 6, y = b & 63;
    int x = threadIdx.x;
    const float* p = yhat + (((long)n * 64) * 64 + y) * 64 + x;
    float s = 0.f;
    #pragma unroll 8
    for (int c = 0; c < 64; ++c) { float v = p[(long)c * 4096]; s += v * v; }
    g_P[n][y][x] = s;
}

__global__ void kNorm() {
    int idx = blockIdx.x * blockDim.x + threadIdx.x;
    int n = idx >> 12, l = idx & 4095;
    int y = l >> 6, x = l & 63;
    float s = 0.f;
    #pragma unroll
    for (int o = 0; o < 4; ++o) {
        int yy = y + c_dy[o], xx = x + c_dx[o];
        if (yy >= 0 && xx >= 0 && xx < 64) s += g_P[n][yy][xx];
    }
    g_rnorm[n][l] = 1.0f / fmaxf(sqrtf(s), 1e-12f);
    ((ull*)g_best)[idx] = 0ull;          // reset per replay
}

// Build fp16x2 splits of normalized features, position-major [n][l][f].
__global__ void __launch_bounds__(256) kSplit(const float* __restrict__ yhat) {
    __shared__ float sT[64][65];
    int b  = blockIdx.x;                  // n*256 + fb*64 + lb
    int lb = b & 63, fb = (b >> 6) & 3, n = b >> 8;
    int tid = threadIdx.x;
    int yy = lb + c_dy[fb];
    {
        int li = tid & 63, fi0 = tid >> 6;
        int l  = lb * 64 + li;
        float rn = g_rnorm[n][l];
        int xx = li + c_dx[fb];
        bool ok = (yy >= 0) && (xx >= 0) && (xx < 64);
        #pragma unroll
        for (int it = 0; it < 16; ++it) {
            int fi = fi0 + it * 4;
            float v = 0.f;
            if (ok) v = yhat[(((long)n * 64 + fi) * 64 + yy) * 64 + xx];
            sT[li][fi] = v * rn;
        }
    }
    __syncthreads();
    {
        int lr = tid >> 2, fq = tid & 3;
        int pos = lb * 64 + lr;
        unsigned u1[8], u2[8];
        #pragma unroll
        for (int k = 0; k < 16; ++k) {
            float v = sT[lr][fq * 16 + k];
            __half h1 = __float2half(v);
            float r1 = v - __half2float(h1);
            __half h2 = __float2half(r1);
            unsigned b1 = __half_as_ushort(h1);
            unsigned b2 = __half_as_ushort(h2);
            int w = k >> 1, sh = (k & 1) * 16;
            if (sh == 0) { u1[w] = b1; u2[w] = b2; }
            else { u1[w] |= b1 << 16; u2[w] |= b2 << 16; }
        }
        int f0 = fb * 64 + fq * 16;
        *(uint4*)&g_Us[0][n][pos][f0]     = *(uint4*)&u1[0];
        *(uint4*)&g_Us[0][n][pos][f0 + 8] = *(uint4*)&u1[4];
        *(uint4*)&g_Us[1][n][pos][f0]     = *(uint4*)&u2[0];
        *(uint4*)&g_Us[1][n][pos][f0 + 8] = *(uint4*)&u2[4];
    }
}

// ---------------------------------------------------------------------------
// fp16x2 mma.sync GEMM. 128x128 tile per job, K=256 in chunks of 32
// (2 sub-chunks of 16 per barrier), 3 product passes per sub-chunk.
// WARP DE-PHASING: warp parity selects pass order (forward/reverse) and
// warp-pair parity selects sub-chunk order, so LDSM phases of half the
// warps overlap MMA phases of the other half (per-warp sum order only).
#define ROWB   48u
#define SPLITB 6144u             // 128*48
#define HALFB  24576u            // 4*SPLITB (one sub-chunk)
#define STAGEB 49152u            // 2 sub-chunks

__global__ void __launch_bounds__(256, 2) kMMA() {
    extern __shared__ __align__(16) char dsm[];
    uint32_t sbase = (uint32_t)__cvta_generic_to_shared(dsm);

    int n = blockIdx.y;
    int b = blockIdx.x;                 // b = mt*(mt+1)/2 + lt
    int mt = (int)((sqrtf(8.f * b + 1.f) - 1.f) * 0.5f);
    while ((mt + 1) * (mt + 2) / 2 <= b) ++mt;
    while (mt * (mt + 1) / 2 > b) --mt;
    int lt = b - mt * (mt + 1) / 2;
    int m0 = mt << 7, l0 = lt << 7;
    bool diag = (lt == mt);
    uint32_t bTile = diag ? 0u : 2u;    // diag: B aliases A tiles

    int tid  = threadIdx.x;
    int w    = tid >> 5, lane = tid & 31;
    int wm   = w & 1, wl = w >> 1;
    int g    = lane >> 2, tig = lane & 3;

    int crow = tid >> 1, chalf = tid & 1;   // cp.async task: (row, 16B half)

    uint32_t aoff[4], boff[2];
    #pragma unroll
    for (int im = 0; im < 4; ++im)
        aoff[im] = (uint32_t)((wm * 64 + im * 16 + (lane & 15)) * ROWB
                              + (lane >> 4) * 16);
    #pragma unroll
    for (int p = 0; p < 2; ++p)
        boff[p] = (uint32_t)((wl * 32 + p * 16 + (lane & 7) + ((lane >> 4) << 3)) * ROWB
                             + (((lane >> 3) & 1) << 4));

    // prefetch chunk 0 (both sub-chunks)
    {
        #pragma unroll
        for (int h = 0; h < 2; ++h) {
            #pragma unroll
            for (int tile = 0; tile < 4; ++tile) {
                if (tile >= 2 && diag) break;
                int sp = tile & 1; bool isB = tile >= 2;
                const __half* src =
                    &g_Us[sp][n][(isB ? l0 : m0) + crow][h * 16] + (chalf << 3);
                CP16(sbase + h * HALFB + tile * SPLITB + crow * ROWB + (chalf << 4), src);
            }
        }
        CP_COMMIT();
    }

    float acc[4][4][4];
    #pragma unroll
    for (int i = 0; i < 4; ++i)
        #pragma unroll
        for (int j = 0; j < 4; ++j)
            #pragma unroll
            for (int r = 0; r < 4; ++r) acc[i][j][r] = 0.f;

    unsigned af[4][4], bf1[4][2], bf2[4][2];
    int wpar = w & 1;                   // pass-order parity
    int hpar = (w >> 1) & 1;            // sub-chunk-order parity

    #pragma unroll 1
    for (int kc = 0; kc < 8; ++kc) {
        CP_WAIT0();
        __syncthreads();
        if (kc < 7) {                   // prefetch next 32-k chunk
            int k0 = (kc + 1) << 5;
            uint32_t st = sbase + (uint32_t)((kc + 1) & 1) * STAGEB;
            #pragma unroll
            for (int h = 0; h < 2; ++h) {
                #pragma unroll
                for (int tile = 0; tile < 4; ++tile) {
                    if (tile >= 2 && diag) break;
                    int sp = tile & 1; bool isB = tile >= 2;
                    const __half* src =
                        &g_Us[sp][n][(isB ? l0 : m0) + crow][k0 + h * 16] + (chalf << 3);
                    CP16(st + h * HALFB + tile * SPLITB + crow * ROWB + (chalf << 4), src);
                }
            }
            CP_COMMIT();
        }

        uint32_t stg = sbase + (uint32_t)(kc & 1) * STAGEB;

        #define LOADA(base) do { \
            LDSM4(af[0][0], af[0][1], af[0][2], af[0][3], (base) + aoff[0]); \
            LDSM4(af[1][0], af[1][1], af[1][2], af[1][3], (base) + aoff[1]); \
            LDSM4(af[2][0], af[2][1], af[2][2], af[2][3], (base) + aoff[2]); \
            LDSM4(af[3][0], af[3][1], af[3][2], af[3][3], (base) + aoff[3]); \
        } while (0)
        #define LOADBx(bfx, base) do { \
            LDSM4(bfx[0][0], bfx[0][1], bfx[1][0], bfx[1][1], (base) + boff[0]); \
            LDSM4(bfx[2][0], bfx[2][1], bfx[3][0], bfx[3][1], (base) + boff[1]); \
        } while (0)
        #define PASSx(bfx) do { \
            _Pragma("unroll") \
            for (int im = 0; im < 4; ++im) \
                _Pragma("unroll") \
                for (int in = 0; in < 4; ++in) \
                    MMA16816(acc[im][in], af[im], bfx[in]); \
        } while (0)

        #pragma unroll
        for (int hh = 0; hh < 2; ++hh) {
            int h = hh ^ hpar;
            uint32_t sA = stg + (uint32_t)h * HALFB;
            uint32_t sB = sA + bTile * SPLITB;
            if (wpar) {
                // forward: A2*B1, A1*B1, A1*B2
                LOADA(sA + SPLITB);
                LOADBx(bf1, sB);
                LOADBx(bf2, sB + SPLITB);
                PASSx(bf1);
                LOADA(sA);
                PASSx(bf1);
                PASSx(bf2);
            } else {
                // reverse: A1*B2, A1*B1, A2*B1
                LOADA(sA);
                LOADBx(bf2, sB + SPLITB);
                LOADBx(bf1, sB);
                PASSx(bf2);
                PASSx(bf1);
                LOADA(sA + SPLITB);
                PASSx(bf1);
            }
        }
    }

    // fold into per-thread best (causal l < m, explicit l tie-break)
    float bestv[8];
    int   bestl[8];
    #pragma unroll
    for (int s = 0; s < 8; ++s) { bestv[s] = -INFINITY; bestl[s] = 0x7fffffff; }

    #pragma unroll
    for (int im = 0; im < 4; ++im) {
        #pragma unroll
        for (int rh = 0; rh < 2; ++rh) {
            int s = im * 2 + rh;
            int m = m0 + wm * 64 + im * 16 + g + rh * 8;
            #pragma unroll
            for (int in = 0; in < 4; ++in) {
                #pragma unroll
                for (int cp = 0; cp < 2; ++cp) {
                    float v = acc[im][in][(rh << 1) | cp];
                    int l = l0 + wl * 32 + in * 8 + 2 * tig + cp;
                    if (l < m && (v > bestv[s] || (v == bestv[s] && l < bestl[s]))) {
                        bestv[s] = v; bestl[s] = l;
                    }
                }
            }
        }
    }

    // cross-thread reduction: m-row has 16 contributors (wl x tig)
    __syncthreads();
    float* rv = (float*)dsm;            // [128][16]
    int*   rl = (int*)(dsm + 8192);     // [128][16]
    #pragma unroll
    for (int im = 0; im < 4; ++im)
        #pragma unroll
        for (int rh = 0; rh < 2; ++rh) {
            int mm = wm * 64 + im * 16 + g + rh * 8;
            rv[mm * 16 + wl * 4 + tig] = bestv[im * 2 + rh];
            rl[mm * 16 + wl * 4 + tig] = bestl[im * 2 + rh];
        }
    __syncthreads();
    if (tid < 128) {
        float bv = rv[tid * 16];
        int   bl = rl[tid * 16];
        #pragma unroll
        for (int u = 1; u < 16; ++u) {
            float v = rv[tid * 16 + u];
            int   l = rl[tid * 16 + u];
            if (v > bv || (v == bv && l < bl)) { bv = v; bl = l; }
        }
        bv += 0.0f;                     // canonicalize -0.0
        ull key = ((ull)sortable(bv) << 32) | (unsigned)(~bl);
        atomicMax(&g_best[n][m0 + tid], key);
    }
}

// ---------------------------------------------------------------------------
__global__ void kFinal(const float* __restrict__ yprob, float* __restrict__ out) {
    int idx = blockIdx.x * blockDim.x + threadIdx.x;
    int n = idx >> 12, m = idx & 4095;
    float S, U, A;
    int bl;
    if (m == 0) {
        S = 1e-8f; U = 1e-8f; A = -1.f; bl = -1;
    } else {
        ull key = g_best[n][m];
        float bv = unsortable((unsigned)(key >> 32));
        bl = (int)(~(unsigned)(key & 0xffffffffu));
        if (bv < 0.f) { bv = 0.f; bl = m; }
        S = fminf(fmaxf(bv, 1e-8f), 1.0f);
        U = fminf(fmaxf(yprob[n * LL + bl], 1e-8f), 1.0f);
        A = (float)bl;
    }
    g_arg[n][m] = bl;
    out[OUT_S + idx] = S;
    out[OUT_U + idx] = U;
    out[OUT_A + idx] = A;
}

// ref_unfold gather, float4-vectorized along m.
__global__ void kOut(const float* __restrict__ yhat, float* __restrict__ out) {
    int e4 = blockIdx.x * blockDim.x + threadIdx.x;   // < NB*576*1024
    int mq = (e4 & 1023) << 2;
    int t  = e4 >> 10;                  // n*576 + f
    int f  = t % 576;
    int n  = t / 576;
    int c  = f / 9, ij = f % 9;
    int i  = ij / 3, j = ij % 3;
    const float* plane = yhat + ((long)n * 64 + c) * 4096;
    float4 v;
    float* vv = (float*)&v;
    #pragma unroll
    for (int q = 0; q < 4; ++q) {
        int m = mq + q;
        float val = 0.f;
        if (m != 0) {
            int a  = g_arg[n][m];
            int ay = a >> 6, ax = a & 63;
            int yy = ay + i - 1, xx = ax + j - 1;
            if (yy >= 0 && yy < 64 && xx >= 0 && xx < 64)
                val = plane[yy * 64 + xx];
        }
        vv[q] = val;
    }
    *(float4*)&out[OUT_R + ((long)t << 12) + mq] = v;
}

// ---------------------------------------------------------------------------
extern "C" void kernel_launch(void* const* d_in, const int* in_sizes, int n_in,
                              void* d_out, int out_size) {
    const float* yhat  = (const float*)d_in[0];
    const float* yprob = (const float*)d_in[1];
    float* out = (float*)d_out;

    cudaFuncSetAttribute(kMMA, cudaFuncAttributeMaxDynamicSharedMemorySize,
                         2 * STAGEB);

    kP<<<NB * 64, 64>>>(yhat);
    kNorm<<<(NB * LL) / 256, 256>>>();
    kSplit<<<NB * 4 * 64, 256>>>(yhat);
    kMMA<<<dim3(528, NB), 256, 2 * STAGEB>>>();
    kFinal<<<(NB * LL) / 256, 256>>>(yprob, out);
    kOut<<<(NB * 576 * 1024) / 256, 256>>>(yhat, out);
}